// round 14
// baseline (speedup 1.0000x reference)
#include <cuda_runtime.h>
#include <cuda_fp16.h>
#include <cstdint>

#define B_ROWS   16384
#define IN_DIM   1024
#define OUT_DIM  1024
#define NGRID    9
#define GRID_LO  (-1.0f)
#define HSTEP    0.25f

#define MTILE 128
#define NTILE 64
#define BK    32
#define KCAT  2048                     // concat-K: 2 segments x 1024
#define MAXT  136                      // <=128 data tiles + <=8 padding tiles
#define STAGES 3
#define A_BYTES 8192                   // 128 rows x 64B
#define B_BYTES 4096                   // 64 rows x 64B
#define STAGE_BYTES (A_BYTES + B_BYTES)      // 12288
#define DSMEM_BYTES (STAGES * STAGE_BYTES)   // 36864

// ---------------- device scratch ----------------
__device__ __half  g_axp[(size_t)MAXT * MTILE * KCAT];       // packed w-scaled X (70MB)
__device__ __half  g_cfp[(size_t)8 * OUT_DIM * KCAT];        // packed pair coeff (32MB)
__device__ int     g_pid[B_ROWS];          // pair id s (pair = {s, s+1})
__device__ float2  g_rw[B_ROWS];           // (w_s, w_{s+1})
__device__ int     g_slot[B_ROWS];         // row -> packed slot
__device__ int     g_hist[8];
__device__ int     g_cursor[8];
__device__ int     g_base[8];              // padded row-slot base per bin
__device__ int     g_perm[MAXT * MTILE];   // slot -> source row (-1 = pad)
__device__ int     g_tpair[MAXT];          // tile -> pair id
__device__ int     g_tact[MAXT];
__device__ int     g_pmask;

// ---------------- helpers ----------------
__device__ __forceinline__ uint32_t smem_u32(const void* p) {
    uint32_t a;
    asm("{ .reg .u64 t; cvta.to.shared.u64 t, %1; cvt.u32.u64 %0, t; }" : "=r"(a) : "l"(p));
    return a;
}
__device__ __forceinline__ void cp16(uint32_t dst, const void* src) {
    asm volatile("cp.async.cg.shared.global [%0], [%1], 16;" :: "r"(dst), "l"(src) : "memory");
}
// swizzled byte offset inside a [rows][32 halfs] tile (64B pitch)
__device__ __forceinline__ uint32_t swz(int r, int c) {
    return (uint32_t)(r * 64 + ((c ^ ((r >> 1) & 3)) << 4));
}
#define LDSM_X4(r0, r1, r2, r3, addr) \
    asm volatile("ldmatrix.sync.aligned.m8n8.x4.shared.b16 {%0,%1,%2,%3}, [%4];" \
        : "=r"(r0), "=r"(r1), "=r"(r2), "=r"(r3) : "r"(addr))
#define MMA16816(d, a, b) \
    asm volatile("mma.sync.aligned.m16n8k16.row.col.f32.f16.f16.f32 " \
        "{%0,%1,%2,%3}, {%4,%5,%6,%7}, {%8,%9}, {%0,%1,%2,%3};" \
        : "+f"((d)[0]), "+f"((d)[1]), "+f"((d)[2]), "+f"((d)[3]) \
        : "r"((a)[0]), "r"((a)[1]), "r"((a)[2]), "r"((a)[3]), "r"((b)[0]), "r"((b)[1]))

// ---------------------------------------------------------------------------
// Kernel 0 (1 block): reset counters
// ---------------------------------------------------------------------------
__global__ void kan_reset_kernel() {
    if (threadIdx.x < 8) { g_hist[threadIdx.x] = 0; g_cursor[threadIdx.x] = 0; }
}

// ---------------------------------------------------------------------------
// Kernel 1: per-row mean -> pair id + 2 normalized hat weights + fused hist
// ---------------------------------------------------------------------------
__global__ void kan_weights_kernel(const float* __restrict__ x) {
    const int row = blockIdx.x;
    const float4 v = reinterpret_cast<const float4*>(x + (size_t)row * IN_DIM)[threadIdx.x];
    float s = v.x + v.y + v.z + v.w;
    #pragma unroll
    for (int o = 16; o > 0; o >>= 1) s += __shfl_xor_sync(0xFFFFFFFFu, s, o);

    __shared__ float warp_sums[8];
    if ((threadIdx.x & 31) == 0) warp_sums[threadIdx.x >> 5] = s;
    __syncthreads();

    if (threadIdx.x == 0) {
        float tot = 0.0f;
        #pragma unroll
        for (int i = 0; i < 8; i++) tot += warp_sums[i];
        const float mean = tot * (1.0f / IN_DIM);
        float w[NGRID]; float sum = 0.0f;
        #pragma unroll
        for (int g = 0; g < NGRID; g++) {
            const float gp = GRID_LO + HSTEP * (float)g;
            float t = 1.0f - fabsf(mean - gp) / HSTEP;
            t = t > 0.0f ? t : 0.0f;
            w[g] = t; sum += t;
        }
        const float inv = 1.0f / (sum + 1e-8f);
        int sg = (int)floorf((mean - GRID_LO) / HSTEP);
        sg = sg < 0 ? 0 : (sg > 7 ? 7 : sg);
        g_pid[row] = sg;
        g_rw[row] = make_float2(w[sg] * inv, w[sg + 1] * inv);
        atomicAdd(&g_hist[sg], 1);
    }
}

// ---------------------------------------------------------------------------
// Kernel 2 (1 block): tile table, bases, perm init, pair mask
// ---------------------------------------------------------------------------
__global__ void kan_plan_kernel() {
    if (threadIdx.x == 0) {
        int T = 0, base = 0, pm = 0;
        #pragma unroll
        for (int p = 0; p < 8; p++) {
            g_base[p] = base;
            const int h = g_hist[p];
            if (h > 0) pm |= (1 << p);
            const int nt = (h + MTILE - 1) / MTILE;
            for (int j = 0; j < nt; j++) { g_tpair[T] = p; g_tact[T] = 1; T++; }
            base += nt * MTILE;
        }
        for (; T < MAXT; T++) g_tact[T] = 0;
        g_pmask = pm;
    }
    for (int i = threadIdx.x; i < MAXT * MTILE; i += blockDim.x) g_perm[i] = -1;
}

// ---------------------------------------------------------------------------
// Kernel 3: scatter rows into padded bins (block-aggregated atomics)
// ---------------------------------------------------------------------------
__global__ void kan_scatter_kernel() {
    __shared__ int cnt[8], basei[8];
    const int tid = threadIdx.x;
    const int row = blockIdx.x * 256 + tid;
    if (tid < 8) cnt[tid] = 0;
    __syncthreads();
    const int p = g_pid[row];
    const int lrank = atomicAdd(&cnt[p], 1);
    __syncthreads();
    if (tid < 8) basei[tid] = atomicAdd(&g_cursor[tid], cnt[tid]);
    __syncthreads();
    const int pos = g_base[p] + basei[p] + lrank;
    g_perm[pos] = row;
    g_slot[row] = pos;
}

// ---------------------------------------------------------------------------
// Kernel 4: w-scaled X -> fp16 packed at the row's slot (concat-K, 2 segs)
// ---------------------------------------------------------------------------
__global__ void kan_scale_kernel(const float* __restrict__ x) {
    const int row = blockIdx.x;
    const int slot = g_slot[row];
    const float2 w2 = g_rw[row];
    const float4 v = reinterpret_cast<const float4*>(x + (size_t)row * IN_DIM)[threadIdx.x];
    __half* dst = g_axp + (size_t)slot * KCAT + threadIdx.x * 4;
    #pragma unroll
    for (int gi = 0; gi < 2; gi++) {
        const float w = gi ? w2.y : w2.x;
        __half2 h0 = __floats2half2_rn(w * v.x, w * v.y);
        __half2 h1 = __floats2half2_rn(w * v.z, w * v.w);
        uint2 u;
        u.x = *reinterpret_cast<uint32_t*>(&h0);
        u.y = *reinterpret_cast<uint32_t*>(&h1);
        *reinterpret_cast<uint2*>(dst + gi * IN_DIM) = u;
    }
}

// ---------------------------------------------------------------------------
// Kernel 5: coeff fp32 -> fp16 packed per active pair (concat-K)
// ---------------------------------------------------------------------------
__global__ void kan_cvt_pair_kernel(const float* __restrict__ coeff) {
    const int p = blockIdx.x >> 10;
    if (!((g_pmask >> p) & 1)) return;
    const int idx = (blockIdx.x & 1023) * 256 + threadIdx.x;  // 0..262143
    const int n  = idx >> 8;
    const int kc = (idx & 255) * 8;
    const int seg = p + (kc >> 10);
    const int k = kc & 1023;
    const float* src = coeff + (size_t)seg * (OUT_DIM * IN_DIM) + (size_t)n * IN_DIM + k;
    const float4 a = *reinterpret_cast<const float4*>(src);
    const float4 b = *reinterpret_cast<const float4*>(src + 4);
    __half2 h0 = __floats2half2_rn(a.x, a.y);
    __half2 h1 = __floats2half2_rn(a.z, a.w);
    __half2 h2 = __floats2half2_rn(b.x, b.y);
    __half2 h3 = __floats2half2_rn(b.z, b.w);
    uint4 u;
    u.x = *reinterpret_cast<uint32_t*>(&h0);
    u.y = *reinterpret_cast<uint32_t*>(&h1);
    u.z = *reinterpret_cast<uint32_t*>(&h2);
    u.w = *reinterpret_cast<uint32_t*>(&h3);
    *reinterpret_cast<uint4*>(g_cfp + (size_t)p * (OUT_DIM * KCAT) + (size_t)n * KCAT + kc) = u;
}

// ---------------------------------------------------------------------------
// Kernel 6: dense HMMA GEMM on packed tiles, K=2048.
// CTA 128x64, BK=32, 3-stage cp.async, 4 warps (2M x 2N), warp 64x32.
// 128 threads/CTA, 4 CTAs/SM -> each barrier drains only 1/4 of the SM.
// ---------------------------------------------------------------------------
__global__ void __launch_bounds__(128, 4)
kan_hmma_kernel(const float* __restrict__ bias, float* __restrict__ out) {
    extern __shared__ unsigned char dyn_smem[];
    __shared__ int s_perm[MTILE];

    const int tid  = threadIdx.x;
    const int wid  = tid >> 5;
    const int lane = tid & 31;
    const int wm = wid >> 1;          // 0..1 -> M offset wm*64
    const int wn = wid & 1;           // 0..1 -> N offset wn*32
    const int t  = blockIdx.y;
    const int n0 = blockIdx.x * NTILE;
    const uint32_t dynb = smem_u32(dyn_smem);

    if (!g_tact[t]) return;
    const int pair = g_tpair[t];
    s_perm[tid] = g_perm[t * MTILE + tid];
    __syncthreads();

    const int total = KCAT / BK;   // 64

    float acc[4][4][4];
    #pragma unroll
    for (int mi = 0; mi < 4; mi++)
        #pragma unroll
        for (int ni = 0; ni < 4; ni++)
            #pragma unroll
            for (int e = 0; e < 4; e++) acc[mi][ni][e] = 0.0f;

    // A loads: thread -> row tid (0..127), chunks 0..3 (64B consecutive)
    const __half* aRow = g_axp + ((size_t)t * MTILE + tid) * KCAT;
    // B loads: thread -> row tid>>1 (0..63), chunk pair (tid&1)*2
    const int blr = tid >> 1;
    const int blc = (tid & 1) * 2;
    const __half* bRow = g_cfp + (size_t)pair * (OUT_DIM * KCAT)
                       + (size_t)(n0 + blr) * KCAT + blc * 8;

    // ---- prologue ----
    #pragma unroll
    for (int s = 0; s < STAGES - 1; s++) {
        {
            const int kb = s * BK;
            const uint32_t sa = dynb + s * STAGE_BYTES;
            #pragma unroll
            for (int c = 0; c < 4; c++)
                cp16(sa + swz(tid, c), aRow + kb + c * 8);
            cp16(sa + A_BYTES + swz(blr, blc),     bRow + kb);
            cp16(sa + A_BYTES + swz(blr, blc + 1), bRow + kb + 8);
        }
        asm volatile("cp.async.commit_group;" ::: "memory");
    }

    // ---- main loop ----
    for (int it = 0; it < total; it++) {
        asm volatile("cp.async.wait_group %0;" :: "n"(STAGES - 2));
        __syncthreads();

        const int nxt = it + STAGES - 1;
        if (nxt < total) {
            const int kb = nxt * BK;
            const uint32_t sa = dynb + (nxt % STAGES) * STAGE_BYTES;
            #pragma unroll
            for (int c = 0; c < 4; c++)
                cp16(sa + swz(tid, c), aRow + kb + c * 8);
            cp16(sa + A_BYTES + swz(blr, blc),     bRow + kb);
            cp16(sa + A_BYTES + swz(blr, blc + 1), bRow + kb + 8);
        }
        asm volatile("cp.async.commit_group;" ::: "memory");

        const uint32_t aBase = dynb + (it % STAGES) * STAGE_BYTES;
        const uint32_t bBase = aBase + A_BYTES;

        #pragma unroll
        for (int h = 0; h < 2; h++) {
            uint32_t a[4][4], b[4][2];
            #pragma unroll
            for (int mi = 0; mi < 4; mi++) {
                const int r = wm * 64 + mi * 16 + (lane & 15);
                const int c = 2 * h + (lane >> 4);
                LDSM_X4(a[mi][0], a[mi][1], a[mi][2], a[mi][3], aBase + swz(r, c));
            }
            #pragma unroll
            for (int nj = 0; nj < 2; nj++) {
                const int r = wn * 32 + nj * 16 + ((lane & 16) >> 1) + (lane & 7);
                const int c = 2 * h + ((lane >> 3) & 1);
                LDSM_X4(b[2 * nj][0], b[2 * nj][1], b[2 * nj + 1][0], b[2 * nj + 1][1],
                        bBase + swz(r, c));
            }
            #pragma unroll
            for (int mi = 0; mi < 4; mi++)
                #pragma unroll
                for (int ni = 0; ni < 4; ni++)
                    MMA16816(acc[mi][ni], a[mi], b[ni]);
        }
    }

    // ---- epilogue: add bias, scatter-store via perm ----
    #pragma unroll
    for (int mi = 0; mi < 4; mi++) {
        const int rt0 = wm * 64 + mi * 16 + (lane >> 2);
        const int pr0 = s_perm[rt0];
        const int pr1 = s_perm[rt0 + 8];
        #pragma unroll
        for (int ni = 0; ni < 4; ni++) {
            const int col = n0 + wn * 32 + ni * 8 + 2 * (lane & 3);
            const float2 bb = *reinterpret_cast<const float2*>(bias + col);
            if (pr0 >= 0) {
                float2 o;
                o.x = acc[mi][ni][0] + bb.x;
                o.y = acc[mi][ni][1] + bb.y;
                *reinterpret_cast<float2*>(&out[(size_t)pr0 * OUT_DIM + col]) = o;
            }
            if (pr1 >= 0) {
                float2 o;
                o.x = acc[mi][ni][2] + bb.x;
                o.y = acc[mi][ni][3] + bb.y;
                *reinterpret_cast<float2*>(&out[(size_t)pr1 * OUT_DIM + col]) = o;
            }
        }
    }
}

// ---------------------------------------------------------------------------
// Launch
// ---------------------------------------------------------------------------
extern "C" void kernel_launch(void* const* d_in, const int* in_sizes, int n_in,
                              void* d_out, int out_size) {
    const float* x     = (const float*)d_in[0];   // (8,2048,1024) fp32
    const float* coeff = (const float*)d_in[1];   // (9,1024,1024) fp32
    const float* bias  = (const float*)d_in[2];   // (1024,)       fp32
    float* out = (float*)d_out;                   // (16384,1024)  fp32

    cudaFuncSetAttribute(kan_hmma_kernel,
                         cudaFuncAttributeMaxDynamicSharedMemorySize, DSMEM_BYTES);

    kan_reset_kernel<<<1, 32>>>();
    kan_weights_kernel<<<B_ROWS, 256>>>(x);
    kan_plan_kernel<<<1, 256>>>();
    kan_scatter_kernel<<<B_ROWS / 256, 256>>>();
    kan_scale_kernel<<<B_ROWS, 256>>>(x);
    kan_cvt_pair_kernel<<<8 * 1024, 256>>>(coeff);

    dim3 grid(OUT_DIM / NTILE, MAXT);   // (16, 136)
    kan_hmma_kernel<<<grid, 128, DSMEM_BYTES>>>(bias, out);
}

// round 15
// speedup vs baseline: 1.3591x; 1.3591x over previous
#include <cuda_runtime.h>
#include <cuda_fp16.h>
#include <cstdint>

#define B_ROWS   16384
#define IN_DIM   1024
#define OUT_DIM  1024
#define NGRID    9
#define GRID_LO  (-1.0f)
#define HSTEP    0.25f

#define MTILE 128
#define NTILE 128
#define BK    32
#define KCAT  2048                     // concat-K: 2 segments x 1024
#define MAXT  136                      // <=128 data tiles + <=8 padding tiles
#define STAGES 6
#define A_BYTES 8192                   // 128 rows x 64B
#define STAGE_BYTES 16384              // A + B
#define DSMEM_BYTES (STAGES * STAGE_BYTES)   // 98304

// ---------------- device scratch ----------------
__device__ __half  g_axp[(size_t)MAXT * MTILE * KCAT];       // packed w-scaled X (70MB)
__device__ __half  g_cfp[(size_t)8 * OUT_DIM * KCAT];        // packed pair coeff (32MB)
__device__ int     g_pid[B_ROWS];          // pair id s (pair = {s, s+1})
__device__ float2  g_rw[B_ROWS];           // (w_s, w_{s+1})
__device__ int     g_slot[B_ROWS];         // row -> packed slot
__device__ int     g_hist[8];
__device__ int     g_cursor[8];
__device__ int     g_base[8];              // padded row-slot base per bin
__device__ int     g_perm[MAXT * MTILE];   // slot -> source row (-1 = pad)
__device__ int     g_tpair[MAXT];          // tile -> pair id
__device__ int     g_tact[MAXT];
__device__ int     g_pmask;

// ---------------- helpers ----------------
__device__ __forceinline__ uint32_t smem_u32(const void* p) {
    uint32_t a;
    asm("{ .reg .u64 t; cvta.to.shared.u64 t, %1; cvt.u32.u64 %0, t; }" : "=r"(a) : "l"(p));
    return a;
}
__device__ __forceinline__ void cp16(uint32_t dst, const void* src) {
    asm volatile("cp.async.cg.shared.global [%0], [%1], 16;" :: "r"(dst), "l"(src) : "memory");
}
// swizzled byte offset inside a [rows][32 halfs] tile (64B pitch)
__device__ __forceinline__ uint32_t swz(int r, int c) {
    return (uint32_t)(r * 64 + ((c ^ ((r >> 1) & 3)) << 4));
}
#define LDSM_X4(r0, r1, r2, r3, addr) \
    asm volatile("ldmatrix.sync.aligned.m8n8.x4.shared.b16 {%0,%1,%2,%3}, [%4];" \
        : "=r"(r0), "=r"(r1), "=r"(r2), "=r"(r3) : "r"(addr))
#define MMA16816(d, a, b) \
    asm volatile("mma.sync.aligned.m16n8k16.row.col.f32.f16.f16.f32 " \
        "{%0,%1,%2,%3}, {%4,%5,%6,%7}, {%8,%9}, {%0,%1,%2,%3};" \
        : "+f"((d)[0]), "+f"((d)[1]), "+f"((d)[2]), "+f"((d)[3]) \
        : "r"((a)[0]), "r"((a)[1]), "r"((a)[2]), "r"((a)[3]), "r"((b)[0]), "r"((b)[1]))

// ---------------------------------------------------------------------------
// Kernel 0 (1 block): reset counters
// ---------------------------------------------------------------------------
__global__ void kan_reset_kernel() {
    if (threadIdx.x < 8) { g_hist[threadIdx.x] = 0; g_cursor[threadIdx.x] = 0; }
}

// ---------------------------------------------------------------------------
// Kernel 1: per-row mean -> pair id + 2 normalized hat weights + fused hist
// ---------------------------------------------------------------------------
__global__ void kan_weights_kernel(const float* __restrict__ x) {
    const int row = blockIdx.x;
    const float4 v = reinterpret_cast<const float4*>(x + (size_t)row * IN_DIM)[threadIdx.x];
    float s = v.x + v.y + v.z + v.w;
    #pragma unroll
    for (int o = 16; o > 0; o >>= 1) s += __shfl_xor_sync(0xFFFFFFFFu, s, o);

    __shared__ float warp_sums[8];
    if ((threadIdx.x & 31) == 0) warp_sums[threadIdx.x >> 5] = s;
    __syncthreads();

    if (threadIdx.x == 0) {
        float tot = 0.0f;
        #pragma unroll
        for (int i = 0; i < 8; i++) tot += warp_sums[i];
        const float mean = tot * (1.0f / IN_DIM);
        float w[NGRID]; float sum = 0.0f;
        #pragma unroll
        for (int g = 0; g < NGRID; g++) {
            const float gp = GRID_LO + HSTEP * (float)g;
            float t = 1.0f - fabsf(mean - gp) / HSTEP;
            t = t > 0.0f ? t : 0.0f;
            w[g] = t; sum += t;
        }
        const float inv = 1.0f / (sum + 1e-8f);
        int sg = (int)floorf((mean - GRID_LO) / HSTEP);
        sg = sg < 0 ? 0 : (sg > 7 ? 7 : sg);
        g_pid[row] = sg;
        g_rw[row] = make_float2(w[sg] * inv, w[sg + 1] * inv);
        atomicAdd(&g_hist[sg], 1);
    }
}

// ---------------------------------------------------------------------------
// Kernel 2 (1 block): tile table, bases, perm init, pair mask
// ---------------------------------------------------------------------------
__global__ void kan_plan_kernel() {
    if (threadIdx.x == 0) {
        int T = 0, base = 0, pm = 0;
        #pragma unroll
        for (int p = 0; p < 8; p++) {
            g_base[p] = base;
            const int h = g_hist[p];
            if (h > 0) pm |= (1 << p);
            const int nt = (h + MTILE - 1) / MTILE;
            for (int j = 0; j < nt; j++) { g_tpair[T] = p; g_tact[T] = 1; T++; }
            base += nt * MTILE;
        }
        for (; T < MAXT; T++) g_tact[T] = 0;
        g_pmask = pm;
    }
    for (int i = threadIdx.x; i < MAXT * MTILE; i += blockDim.x) g_perm[i] = -1;
}

// ---------------------------------------------------------------------------
// Kernel 3: scatter rows into padded bins (block-aggregated atomics)
// ---------------------------------------------------------------------------
__global__ void kan_scatter_kernel() {
    __shared__ int cnt[8], basei[8];
    const int tid = threadIdx.x;
    const int row = blockIdx.x * 256 + tid;
    if (tid < 8) cnt[tid] = 0;
    __syncthreads();
    const int p = g_pid[row];
    const int lrank = atomicAdd(&cnt[p], 1);
    __syncthreads();
    if (tid < 8) basei[tid] = atomicAdd(&g_cursor[tid], cnt[tid]);
    __syncthreads();
    const int pos = g_base[p] + basei[p] + lrank;
    g_perm[pos] = row;
    g_slot[row] = pos;
}

// ---------------------------------------------------------------------------
// Kernel 4: w-scaled X -> fp16 packed at the row's slot (concat-K, 2 segs)
// ---------------------------------------------------------------------------
__global__ void kan_scale_kernel(const float* __restrict__ x) {
    const int row = blockIdx.x;
    const int slot = g_slot[row];
    const float2 w2 = g_rw[row];
    const float4 v = reinterpret_cast<const float4*>(x + (size_t)row * IN_DIM)[threadIdx.x];
    __half* dst = g_axp + (size_t)slot * KCAT + threadIdx.x * 4;
    #pragma unroll
    for (int gi = 0; gi < 2; gi++) {
        const float w = gi ? w2.y : w2.x;
        __half2 h0 = __floats2half2_rn(w * v.x, w * v.y);
        __half2 h1 = __floats2half2_rn(w * v.z, w * v.w);
        uint2 u;
        u.x = *reinterpret_cast<uint32_t*>(&h0);
        u.y = *reinterpret_cast<uint32_t*>(&h1);
        *reinterpret_cast<uint2*>(dst + gi * IN_DIM) = u;
    }
}

// ---------------------------------------------------------------------------
// Kernel 5: coeff fp32 -> fp16 packed per active pair (concat-K)
// ---------------------------------------------------------------------------
__global__ void kan_cvt_pair_kernel(const float* __restrict__ coeff) {
    const int p = blockIdx.x >> 10;
    if (!((g_pmask >> p) & 1)) return;
    const int idx = (blockIdx.x & 1023) * 256 + threadIdx.x;  // 0..262143
    const int n  = idx >> 8;
    const int kc = (idx & 255) * 8;
    const int seg = p + (kc >> 10);
    const int k = kc & 1023;
    const float* src = coeff + (size_t)seg * (OUT_DIM * IN_DIM) + (size_t)n * IN_DIM + k;
    const float4 a = *reinterpret_cast<const float4*>(src);
    const float4 b = *reinterpret_cast<const float4*>(src + 4);
    __half2 h0 = __floats2half2_rn(a.x, a.y);
    __half2 h1 = __floats2half2_rn(a.z, a.w);
    __half2 h2 = __floats2half2_rn(b.x, b.y);
    __half2 h3 = __floats2half2_rn(b.z, b.w);
    uint4 u;
    u.x = *reinterpret_cast<uint32_t*>(&h0);
    u.y = *reinterpret_cast<uint32_t*>(&h1);
    u.z = *reinterpret_cast<uint32_t*>(&h2);
    u.w = *reinterpret_cast<uint32_t*>(&h3);
    *reinterpret_cast<uint4*>(g_cfp + (size_t)p * (OUT_DIM * KCAT) + (size_t)n * KCAT + kc) = u;
}

// ---------------------------------------------------------------------------
// Kernel 6: dense HMMA GEMM on packed tiles, K=2048.
// CTA 128x128, BK=32, 6-stage cp.async processed in PAIRS:
// one __syncthreads + one wait_group per 2 k-chunks (32 barriers, not 64).
// 8 warps (2M x 4N), warp 64x32, 2 CTAs/SM.
// ---------------------------------------------------------------------------
__global__ void __launch_bounds__(256, 2)
kan_hmma_kernel(const float* __restrict__ bias, float* __restrict__ out) {
    extern __shared__ unsigned char dyn_smem[];
    __shared__ int s_perm[MTILE];

    const int tid  = threadIdx.x;
    const int wid  = tid >> 5;
    const int lane = tid & 31;
    const int wm = wid >> 2;          // 0..1 -> M offset wm*64
    const int wn = wid & 3;           // 0..3 -> N offset wn*32
    const int t  = blockIdx.y;
    const int n0 = blockIdx.x * NTILE;
    const uint32_t dynb = smem_u32(dyn_smem);

    if (!g_tact[t]) return;
    const int pair = g_tpair[t];
    if (tid < MTILE) s_perm[tid] = g_perm[t * MTILE + tid];
    __syncthreads();

    float acc[4][4][4];
    #pragma unroll
    for (int mi = 0; mi < 4; mi++)
        #pragma unroll
        for (int ni = 0; ni < 4; ni++)
            #pragma unroll
            for (int e = 0; e < 4; e++) acc[mi][ni][e] = 0.0f;

    const int lr = tid >> 1;            // row 0..127
    const int lc = (tid & 1) * 2;       // chunk 0 or 2
    const __half* aRow = g_axp + ((size_t)t * MTILE + lr) * KCAT + lc * 8;
    const __half* bRow = g_cfp + (size_t)pair * (OUT_DIM * KCAT) + (size_t)(n0 + lr) * KCAT + lc * 8;

    // ---- prologue: fill chunk-pairs 0 and 1 (stages 0..3), one group each ----
    #pragma unroll
    for (int pp = 0; pp < 2; pp++) {
        #pragma unroll
        for (int s2 = 0; s2 < 2; s2++) {
            const int ch = pp * 2 + s2;
            const int kb = ch * BK;
            const uint32_t sa = dynb + ch * STAGE_BYTES;   // stage == ch for ch<6
            cp16(sa + swz(lr, lc),               aRow + kb);
            cp16(sa + swz(lr, lc + 1),           aRow + kb + 8);
            cp16(sa + A_BYTES + swz(lr, lc),     bRow + kb);
            cp16(sa + A_BYTES + swz(lr, lc + 1), bRow + kb + 8);
        }
        asm volatile("cp.async.commit_group;" ::: "memory");
    }

    // ---- main loop: 32 chunk-pairs, one barrier per pair ----
    for (int j = 0; j < 32; j++) {
        asm volatile("cp.async.wait_group 1;" ::: "memory");
        __syncthreads();

        // prefetch chunk-pair j+2 (chunks 2j+4, 2j+5)
        const int pc = 2 * j + 4;
        if (pc < 64) {
            #pragma unroll
            for (int s2 = 0; s2 < 2; s2++) {
                const int ch = pc + s2;
                const int kb = ch * BK;
                const uint32_t sa = dynb + (ch % STAGES) * STAGE_BYTES;
                cp16(sa + swz(lr, lc),               aRow + kb);
                cp16(sa + swz(lr, lc + 1),           aRow + kb + 8);
                cp16(sa + A_BYTES + swz(lr, lc),     bRow + kb);
                cp16(sa + A_BYTES + swz(lr, lc + 1), bRow + kb + 8);
            }
        }
        asm volatile("cp.async.commit_group;" ::: "memory");

        // compute chunks 2j and 2j+1
        #pragma unroll
        for (int s2 = 0; s2 < 2; s2++) {
            const int ch = 2 * j + s2;
            const uint32_t aBase = dynb + (ch % STAGES) * STAGE_BYTES;
            const uint32_t bBase = aBase + A_BYTES;

            #pragma unroll
            for (int h = 0; h < 2; h++) {
                uint32_t a[4][4], b[4][2];
                #pragma unroll
                for (int mi = 0; mi < 4; mi++) {
                    const int r = wm * 64 + mi * 16 + (lane & 15);
                    const int c = 2 * h + (lane >> 4);
                    LDSM_X4(a[mi][0], a[mi][1], a[mi][2], a[mi][3], aBase + swz(r, c));
                }
                #pragma unroll
                for (int nj = 0; nj < 2; nj++) {
                    const int r = wn * 32 + nj * 16 + ((lane & 16) >> 1) + (lane & 7);
                    const int c = 2 * h + ((lane >> 3) & 1);
                    LDSM_X4(b[2 * nj][0], b[2 * nj][1], b[2 * nj + 1][0], b[2 * nj + 1][1],
                            bBase + swz(r, c));
                }
                #pragma unroll
                for (int mi = 0; mi < 4; mi++)
                    #pragma unroll
                    for (int ni = 0; ni < 4; ni++)
                        MMA16816(acc[mi][ni], a[mi], b[ni]);
            }
        }
    }

    // ---- epilogue: add bias, scatter-store via perm ----
    #pragma unroll
    for (int mi = 0; mi < 4; mi++) {
        const int rt0 = wm * 64 + mi * 16 + (lane >> 2);
        const int pr0 = s_perm[rt0];
        const int pr1 = s_perm[rt0 + 8];
        #pragma unroll
        for (int ni = 0; ni < 4; ni++) {
            const int col = n0 + wn * 32 + ni * 8 + 2 * (lane & 3);
            const float2 bb = *reinterpret_cast<const float2*>(bias + col);
            if (pr0 >= 0) {
                float2 o;
                o.x = acc[mi][ni][0] + bb.x;
                o.y = acc[mi][ni][1] + bb.y;
                *reinterpret_cast<float2*>(&out[(size_t)pr0 * OUT_DIM + col]) = o;
            }
            if (pr1 >= 0) {
                float2 o;
                o.x = acc[mi][ni][2] + bb.x;
                o.y = acc[mi][ni][3] + bb.y;
                *reinterpret_cast<float2*>(&out[(size_t)pr1 * OUT_DIM + col]) = o;
            }
        }
    }
}

// ---------------------------------------------------------------------------
// Launch
// ---------------------------------------------------------------------------
extern "C" void kernel_launch(void* const* d_in, const int* in_sizes, int n_in,
                              void* d_out, int out_size) {
    const float* x     = (const float*)d_in[0];   // (8,2048,1024) fp32
    const float* coeff = (const float*)d_in[1];   // (9,1024,1024) fp32
    const float* bias  = (const float*)d_in[2];   // (1024,)       fp32
    float* out = (float*)d_out;                   // (16384,1024)  fp32

    cudaFuncSetAttribute(kan_hmma_kernel,
                         cudaFuncAttributeMaxDynamicSharedMemorySize, DSMEM_BYTES);

    kan_reset_kernel<<<1, 32>>>();
    kan_weights_kernel<<<B_ROWS, 256>>>(x);
    kan_plan_kernel<<<1, 256>>>();
    kan_scatter_kernel<<<B_ROWS / 256, 256>>>();
    kan_scale_kernel<<<B_ROWS, 256>>>(x);
    kan_cvt_pair_kernel<<<8 * 1024, 256>>>(coeff);

    dim3 grid(OUT_DIM / NTILE, MAXT);   // (8, 136)
    kan_hmma_kernel<<<grid, 256, DSMEM_BYTES>>>(bias, out);
}

// round 17
// speedup vs baseline: 1.5455x; 1.1371x over previous
#include <cuda_runtime.h>
#include <cuda_fp16.h>
#include <cstdint>

#define B_ROWS   16384
#define IN_DIM   1024
#define OUT_DIM  1024
#define NGRID    9
#define GRID_LO  (-1.0f)
#define HSTEP    0.25f

#define MTILE 128
#define NTILE 128
#define BK    32
#define KCAT  2048                     // concat-K: 2 segments x 1024
#define MAXT  136                      // <=128 data tiles + <=8 padding tiles
#define STAGES 3
#define A_BYTES 8192                   // 128 rows x 64B
#define STAGE_BYTES 16384              // A + B
#define DSMEM_BYTES (STAGES * STAGE_BYTES)   // 49152

// ---------------- device scratch ----------------
__device__ __half  g_axn[(size_t)B_ROWS * KCAT];             // w-scaled X, natural row order (67MB)
__device__ __half  g_cfp[(size_t)8 * OUT_DIM * KCAT];        // packed pair coeff (32MB)
__device__ int     g_pid[B_ROWS];          // pair id s (pair = {s, s+1})
__device__ int     g_hist[8];
__device__ int     g_cursor[8];
__device__ int     g_base[8];              // padded row-slot base per bin
__device__ int     g_perm[MAXT * MTILE];   // slot -> source row (-1 = pad)
__device__ int     g_tpair[MAXT];          // tile -> pair id
__device__ int     g_tact[MAXT];
__device__ int     g_pmask;

// ---------------- helpers ----------------
__device__ __forceinline__ uint32_t smem_u32(const void* p) {
    uint32_t a;
    asm("{ .reg .u64 t; cvta.to.shared.u64 t, %1; cvt.u32.u64 %0, t; }" : "=r"(a) : "l"(p));
    return a;
}
__device__ __forceinline__ void cp16(uint32_t dst, const void* src) {
    asm volatile("cp.async.cg.shared.global [%0], [%1], 16;" :: "r"(dst), "l"(src) : "memory");
}
// swizzled byte offset inside a [rows][32 halfs] tile (64B pitch)
__device__ __forceinline__ uint32_t swz(int r, int c) {
    return (uint32_t)(r * 64 + ((c ^ ((r >> 1) & 3)) << 4));
}
#define LDSM_X4(r0, r1, r2, r3, addr) \
    asm volatile("ldmatrix.sync.aligned.m8n8.x4.shared.b16 {%0,%1,%2,%3}, [%4];" \
        : "=r"(r0), "=r"(r1), "=r"(r2), "=r"(r3) : "r"(addr))
#define MMA16816(d, a, b) \
    asm volatile("mma.sync.aligned.m16n8k16.row.col.f32.f16.f16.f32 " \
        "{%0,%1,%2,%3}, {%4,%5,%6,%7}, {%8,%9}, {%0,%1,%2,%3};" \
        : "+f"((d)[0]), "+f"((d)[1]), "+f"((d)[2]), "+f"((d)[3]) \
        : "r"((a)[0]), "r"((a)[1]), "r"((a)[2]), "r"((a)[3]), "r"((b)[0]), "r"((b)[1]))

// ---------------------------------------------------------------------------
// Kernel 0 (1 block): reset counters
// ---------------------------------------------------------------------------
__global__ void kan_reset_kernel() {
    if (threadIdx.x < 8) { g_hist[threadIdx.x] = 0; g_cursor[threadIdx.x] = 0; }
}

// ---------------------------------------------------------------------------
// Kernel 1: fused per-row mean -> pair + weights -> scaled fp16 A (both segs)
// x row is already in registers from the mean reduce; write scaled copy here.
// ---------------------------------------------------------------------------
__global__ void kan_weights_scale_kernel(const float* __restrict__ x) {
    __shared__ float warp_sums[8];
    __shared__ float s_w0, s_w1;

    const int row = blockIdx.x;
    const float4 v = reinterpret_cast<const float4*>(x + (size_t)row * IN_DIM)[threadIdx.x];
    float s = v.x + v.y + v.z + v.w;
    #pragma unroll
    for (int o = 16; o > 0; o >>= 1) s += __shfl_xor_sync(0xFFFFFFFFu, s, o);
    if ((threadIdx.x & 31) == 0) warp_sums[threadIdx.x >> 5] = s;
    __syncthreads();

    if (threadIdx.x == 0) {
        float tot = 0.0f;
        #pragma unroll
        for (int i = 0; i < 8; i++) tot += warp_sums[i];
        const float mean = tot * (1.0f / IN_DIM);
        float w[NGRID]; float sum = 0.0f;
        #pragma unroll
        for (int g = 0; g < NGRID; g++) {
            const float gp = GRID_LO + HSTEP * (float)g;
            float t = 1.0f - fabsf(mean - gp) / HSTEP;
            t = t > 0.0f ? t : 0.0f;
            w[g] = t; sum += t;
        }
        const float inv = 1.0f / (sum + 1e-8f);
        int sg = (int)floorf((mean - GRID_LO) / HSTEP);
        sg = sg < 0 ? 0 : (sg > 7 ? 7 : sg);
        g_pid[row] = sg;
        s_w0 = w[sg] * inv;
        s_w1 = w[sg + 1] * inv;
        atomicAdd(&g_hist[sg], 1);
    }
    __syncthreads();

    const float w0 = s_w0, w1 = s_w1;
    __half* dst = g_axn + (size_t)row * KCAT + threadIdx.x * 4;
    {
        __half2 h0 = __floats2half2_rn(w0 * v.x, w0 * v.y);
        __half2 h1 = __floats2half2_rn(w0 * v.z, w0 * v.w);
        uint2 u;
        u.x = *reinterpret_cast<uint32_t*>(&h0);
        u.y = *reinterpret_cast<uint32_t*>(&h1);
        *reinterpret_cast<uint2*>(dst) = u;
    }
    {
        __half2 h0 = __floats2half2_rn(w1 * v.x, w1 * v.y);
        __half2 h1 = __floats2half2_rn(w1 * v.z, w1 * v.w);
        uint2 u;
        u.x = *reinterpret_cast<uint32_t*>(&h0);
        u.y = *reinterpret_cast<uint32_t*>(&h1);
        *reinterpret_cast<uint2*>(dst + IN_DIM) = u;
    }
}

// ---------------------------------------------------------------------------
// Kernel 2 (1 block): tile table, bases, perm init, pair mask
// ---------------------------------------------------------------------------
__global__ void kan_plan_kernel() {
    if (threadIdx.x == 0) {
        int T = 0, base = 0, pm = 0;
        #pragma unroll
        for (int p = 0; p < 8; p++) {
            g_base[p] = base;
            const int h = g_hist[p];
            if (h > 0) pm |= (1 << p);
            const int nt = (h + MTILE - 1) / MTILE;
            for (int j = 0; j < nt; j++) { g_tpair[T] = p; g_tact[T] = 1; T++; }
            base += nt * MTILE;
        }
        for (; T < MAXT; T++) g_tact[T] = 0;
        g_pmask = pm;
    }
    for (int i = threadIdx.x; i < MAXT * MTILE; i += blockDim.x) g_perm[i] = -1;
}

// ---------------------------------------------------------------------------
// Kernel 3: scatter rows into padded bins (block-aggregated atomics)
// ---------------------------------------------------------------------------
__global__ void kan_scatter_kernel() {
    __shared__ int cnt[8], basei[8];
    const int tid = threadIdx.x;
    const int row = blockIdx.x * 256 + tid;
    if (tid < 8) cnt[tid] = 0;
    __syncthreads();
    const int p = g_pid[row];
    const int lrank = atomicAdd(&cnt[p], 1);
    __syncthreads();
    if (tid < 8) basei[tid] = atomicAdd(&g_cursor[tid], cnt[tid]);
    __syncthreads();
    g_perm[g_base[p] + basei[p] + lrank] = row;
}

// ---------------------------------------------------------------------------
// Kernel 4: coeff fp32 -> fp16 packed per active pair (concat-K)
// ---------------------------------------------------------------------------
__global__ void kan_cvt_pair_kernel(const float* __restrict__ coeff) {
    const int p = blockIdx.x >> 10;
    if (!((g_pmask >> p) & 1)) return;
    const int idx = (blockIdx.x & 1023) * 256 + threadIdx.x;  // 0..262143
    const int n  = idx >> 8;
    const int kc = (idx & 255) * 8;
    const int seg = p + (kc >> 10);
    const int k = kc & 1023;
    const float* src = coeff + (size_t)seg * (OUT_DIM * IN_DIM) + (size_t)n * IN_DIM + k;
    const float4 a = *reinterpret_cast<const float4*>(src);
    const float4 b = *reinterpret_cast<const float4*>(src + 4);
    __half2 h0 = __floats2half2_rn(a.x, a.y);
    __half2 h1 = __floats2half2_rn(a.z, a.w);
    __half2 h2 = __floats2half2_rn(b.x, b.y);
    __half2 h3 = __floats2half2_rn(b.z, b.w);
    uint4 u;
    u.x = *reinterpret_cast<uint32_t*>(&h0);
    u.y = *reinterpret_cast<uint32_t*>(&h1);
    u.z = *reinterpret_cast<uint32_t*>(&h2);
    u.w = *reinterpret_cast<uint32_t*>(&h3);
    *reinterpret_cast<uint4*>(g_cfp + (size_t)p * (OUT_DIM * KCAT) + (size_t)n * KCAT + kc) = u;
}

// ---------------------------------------------------------------------------
// Kernel 5: dense HMMA GEMM, K=2048, A rows gathered via perm (L2-resident).
// CTA 128x128, BK=32, 3-stage cp.async, 8 warps (2M x 4N), warp 64x32.
// ---------------------------------------------------------------------------
__global__ void __launch_bounds__(256, 2)
kan_hmma_kernel(const float* __restrict__ bias, float* __restrict__ out) {
    extern __shared__ unsigned char dyn_smem[];
    __shared__ int s_perm[MTILE];

    const int tid  = threadIdx.x;
    const int wid  = tid >> 5;
    const int lane = tid & 31;
    const int wm = wid >> 2;          // 0..1 -> M offset wm*64
    const int wn = wid & 3;           // 0..3 -> N offset wn*32
    const int t  = blockIdx.y;
    const int n0 = blockIdx.x * NTILE;
    const uint32_t dynb = smem_u32(dyn_smem);

    if (!g_tact[t]) return;
    const int pair = g_tpair[t];
    if (tid < MTILE) s_perm[tid] = g_perm[t * MTILE + tid];
    __syncthreads();

    const int total = KCAT / BK;   // 64

    float acc[4][4][4];
    #pragma unroll
    for (int mi = 0; mi < 4; mi++)
        #pragma unroll
        for (int ni = 0; ni < 4; ni++)
            #pragma unroll
            for (int e = 0; e < 4; e++) acc[mi][ni][e] = 0.0f;

    const int lr = tid >> 1;            // row 0..127
    const int lc = (tid & 1) * 2;       // chunk 0 or 2
    int arow = s_perm[lr];
    if (arow < 0) arow = 0;             // pad rows: harmless data, never stored
    const __half* aRow = g_axn + (size_t)arow * KCAT + lc * 8;
    const __half* bRow = g_cfp + (size_t)pair * (OUT_DIM * KCAT) + (size_t)(n0 + lr) * KCAT + lc * 8;

    // ---- prologue ----
    #pragma unroll
    for (int s = 0; s < STAGES - 1; s++) {
        {
            const int kb = s * BK;
            const uint32_t sa = dynb + s * STAGE_BYTES;
            cp16(sa + swz(lr, lc),               aRow + kb);
            cp16(sa + swz(lr, lc + 1),           aRow + kb + 8);
            cp16(sa + A_BYTES + swz(lr, lc),     bRow + kb);
            cp16(sa + A_BYTES + swz(lr, lc + 1), bRow + kb + 8);
        }
        asm volatile("cp.async.commit_group;" ::: "memory");
    }

    // ---- main loop ----
    for (int it = 0; it < total; it++) {
        asm volatile("cp.async.wait_group %0;" :: "n"(STAGES - 2));
        __syncthreads();

        const int nxt = it + STAGES - 1;
        if (nxt < total) {
            const int kb = nxt * BK;
            const uint32_t sa = dynb + (nxt % STAGES) * STAGE_BYTES;
            cp16(sa + swz(lr, lc),               aRow + kb);
            cp16(sa + swz(lr, lc + 1),           aRow + kb + 8);
            cp16(sa + A_BYTES + swz(lr, lc),     bRow + kb);
            cp16(sa + A_BYTES + swz(lr, lc + 1), bRow + kb + 8);
        }
        asm volatile("cp.async.commit_group;" ::: "memory");

        const uint32_t aBase = dynb + (it % STAGES) * STAGE_BYTES;
        const uint32_t bBase = aBase + A_BYTES;

        #pragma unroll
        for (int h = 0; h < 2; h++) {
            uint32_t a[4][4], b[4][2];
            #pragma unroll
            for (int mi = 0; mi < 4; mi++) {
                const int r = wm * 64 + mi * 16 + (lane & 15);
                const int c = 2 * h + (lane >> 4);
                LDSM_X4(a[mi][0], a[mi][1], a[mi][2], a[mi][3], aBase + swz(r, c));
            }
            #pragma unroll
            for (int nj = 0; nj < 2; nj++) {
                const int r = wn * 32 + nj * 16 + ((lane & 16) >> 1) + (lane & 7);
                const int c = 2 * h + ((lane >> 3) & 1);
                LDSM_X4(b[2 * nj][0], b[2 * nj][1], b[2 * nj + 1][0], b[2 * nj + 1][1],
                        bBase + swz(r, c));
            }
            #pragma unroll
            for (int mi = 0; mi < 4; mi++)
                #pragma unroll
                for (int ni = 0; ni < 4; ni++)
                    MMA16816(acc[mi][ni], a[mi], b[ni]);
        }
    }

    // ---- epilogue: add bias, scatter-store via perm ----
    #pragma unroll
    for (int mi = 0; mi < 4; mi++) {
        const int rt0 = wm * 64 + mi * 16 + (lane >> 2);
        const int pr0 = s_perm[rt0];
        const int pr1 = s_perm[rt0 + 8];
        #pragma unroll
        for (int ni = 0; ni < 4; ni++) {
            const int col = n0 + wn * 32 + ni * 8 + 2 * (lane & 3);
            const float2 bb = *reinterpret_cast<const float2*>(bias + col);
            if (pr0 >= 0) {
                float2 o;
                o.x = acc[mi][ni][0] + bb.x;
                o.y = acc[mi][ni][1] + bb.y;
                *reinterpret_cast<float2*>(&out[(size_t)pr0 * OUT_DIM + col]) = o;
            }
            if (pr1 >= 0) {
                float2 o;
                o.x = acc[mi][ni][2] + bb.x;
                o.y = acc[mi][ni][3] + bb.y;
                *reinterpret_cast<float2*>(&out[(size_t)pr1 * OUT_DIM + col]) = o;
            }
        }
    }
}

// ---------------------------------------------------------------------------
// Launch
// ---------------------------------------------------------------------------
extern "C" void kernel_launch(void* const* d_in, const int* in_sizes, int n_in,
                              void* d_out, int out_size) {
    const float* x     = (const float*)d_in[0];   // (8,2048,1024) fp32
    const float* coeff = (const float*)d_in[1];   // (9,1024,1024) fp32
    const float* bias  = (const float*)d_in[2];   // (1024,)       fp32
    float* out = (float*)d_out;                   // (16384,1024)  fp32

    cudaFuncSetAttribute(kan_hmma_kernel,
                         cudaFuncAttributeMaxDynamicSharedMemorySize, DSMEM_BYTES);

    kan_reset_kernel<<<1, 32>>>();
    kan_weights_scale_kernel<<<B_ROWS, 256>>>(x);
    kan_plan_kernel<<<1, 256>>>();
    kan_scatter_kernel<<<B_ROWS / 256, 256>>>();
    kan_cvt_pair_kernel<<<8 * 1024, 256>>>(coeff);

    dim3 grid(OUT_DIM / NTILE, MAXT);   // (8, 136)
    kan_hmma_kernel<<<grid, 256, DSMEM_BYTES>>>(bias, out);
}